// round 14
// baseline (speedup 1.0000x reference)
#include <cuda_runtime.h>
#include <cuda_bf16.h>
#include <math_constants.h>
#include <cstdint>

#define T_LEN   4096
#define DIM     1024
#define QKV_DIM 3072
#define MLP_DIM 4096
#define NHEADS  16
#define HD      64
#define WIN     512
#define EPS_F   1.1920929e-07f

// ================= helpers =================
__device__ __forceinline__ uint32_t smem_u32(const void* p) {
    uint32_t a;
    asm("{ .reg .u64 t; cvta.to.shared.u64 t, %1; cvt.u32.u64 %0, t; }" : "=r"(a) : "l"(p));
    return a;
}
__device__ __forceinline__ void cp16(uint32_t s, const void* g) {
    asm volatile("cp.async.cg.shared.global [%0], [%1], 16;" :: "r"(s), "l"(g));
}
__device__ __forceinline__ void ldsm_x4(uint32_t* r, uint32_t addr) {
    asm volatile("ldmatrix.sync.aligned.m8n8.x4.shared.b16 {%0,%1,%2,%3}, [%4];"
                 : "=r"(r[0]), "=r"(r[1]), "=r"(r[2]), "=r"(r[3]) : "r"(addr));
}
__device__ __forceinline__ void ldsm_x4_t(uint32_t* r, uint32_t addr) {
    asm volatile("ldmatrix.sync.aligned.m8n8.x4.trans.shared.b16 {%0,%1,%2,%3}, [%4];"
                 : "=r"(r[0]), "=r"(r[1]), "=r"(r[2]), "=r"(r[3]) : "r"(addr));
}
__device__ __forceinline__ void mma16816(float* c, const uint32_t* a, const uint32_t* b) {
    asm volatile("mma.sync.aligned.m16n8k16.row.col.f32.bf16.bf16.f32 "
        "{%0,%1,%2,%3}, {%4,%5,%6,%7}, {%8,%9}, {%0,%1,%2,%3};"
        : "+f"(c[0]), "+f"(c[1]), "+f"(c[2]), "+f"(c[3])
        : "r"(a[0]), "r"(a[1]), "r"(a[2]), "r"(a[3]), "r"(b[0]), "r"(b[1]));
}
__device__ __forceinline__ void imma16832(int* c, const uint32_t* a, const uint32_t* b) {
    asm volatile("mma.sync.aligned.m16n8k32.row.col.s32.s8.s8.s32 "
        "{%0,%1,%2,%3}, {%4,%5,%6,%7}, {%8,%9}, {%0,%1,%2,%3};"
        : "+r"(c[0]), "+r"(c[1]), "+r"(c[2]), "+r"(c[3])
        : "r"(a[0]), "r"(a[1]), "r"(a[2]), "r"(a[3]), "r"(b[0]), "r"(b[1]));
}
__device__ __forceinline__ uint32_t pack2(__nv_bfloat16 a, __nv_bfloat16 b) {
    return (uint32_t)__bfloat16_as_ushort(a) | ((uint32_t)__bfloat16_as_ushort(b) << 16);
}
__device__ __forceinline__ uint32_t pack_hi(float a, float b) {
    return pack2(__float2bfloat16(a), __float2bfloat16(b));
}

#define MBARRIER_INIT(addr, cnt) \
    asm volatile("mbarrier.init.shared.b64 [%0], %1;" :: "r"((uint32_t)(addr)), "r"((uint32_t)(cnt)) : "memory")
#define MBARRIER_ARRIVE(addr) \
    asm volatile("mbarrier.arrive.shared::cta.b64 _, [%0];" :: "r"((uint32_t)(addr)) : "memory")
#define CPASYNC_MBAR_ARRIVE(addr) \
    asm volatile("cp.async.mbarrier.arrive.noinc.shared::cta.b64 [%0];" :: "r"((uint32_t)(addr)) : "memory")
#define MBARRIER_WAIT_PARITY(addr, par) do { \
    uint32_t _m = (uint32_t)(addr); uint32_t _p = (uint32_t)(par); uint32_t _d; \
    asm volatile("{\n\t.reg .pred p;\n\tmbarrier.try_wait.parity.acquire.cta.shared::cta.b64 p, [%1], %2;\n\tselp.b32 %0, 1, 0, p;\n\t}" \
        : "=r"(_d) : "r"(_m), "r"(_p) : "memory"); \
    if (!_d) { \
        asm volatile("{\n\t.reg .pred P1;\n\tWL_%=:\n\tmbarrier.try_wait.parity.acquire.cta.shared::cta.b64 P1, [%0], %1, 0x989680;\n\t@P1 bra.uni WD_%=;\n\tbra.uni WL_%=;\n\tWD_%=:\n\t}" \
            :: "r"(_m), "r"(_p) : "memory"); \
    } } while (0)

// ================= scratch =================
__device__ float g_qkv [T_LEN * QKV_DIM];
__device__ float g_x1  [T_LEN * DIM];
__device__ float g_attn[T_LEN * DIM];
__device__ float g_hf  [T_LEN * MLP_DIM];
__device__ float2 g_rope[T_LEN * 16];

#define BF16A __device__ __align__(16) __nv_bfloat16
BF16A g_qb[T_LEN * DIM];
BF16A g_kb[T_LEN * DIM];
BF16A g_vb[T_LEN * DIM];

#define I8A __device__ __align__(16) int8_t
I8A g_xq [T_LEN * DIM];     __device__ float g_sx [T_LEN];
I8A g_aq [T_LEN * DIM];     __device__ float g_sa [T_LEN];
I8A g_x1q[T_LEN * DIM];     __device__ float g_sx1[T_LEN];
I8A g_hq [T_LEN * MLP_DIM]; __device__ float g_sh [T_LEN];
I8A g_wq [QKV_DIM * DIM];   __device__ float g_swq[QKV_DIM];
I8A g_wo [DIM * DIM];       __device__ float g_swo[DIM];
I8A g_w1q[MLP_DIM * DIM];   __device__ float g_sw1[MLP_DIM];
I8A g_w2q[DIM * MLP_DIM];   __device__ float g_sw2[DIM];

// ================= single-digit row quantization =================
__device__ __forceinline__ float block_max256(float v, float* red) {
    #pragma unroll
    for (int off = 16; off; off >>= 1) v = fmaxf(v, __shfl_xor_sync(0xffffffffu, v, off));
    if ((threadIdx.x & 31) == 0) red[threadIdx.x >> 5] = v;
    __syncthreads();
    float m = red[0];
    #pragma unroll
    for (int i = 1; i < 8; i++) m = fmaxf(m, red[i]);
    return m;
}
__device__ __forceinline__ char4 quant4s(float4 v, float invS) {
    return make_char4((signed char)__float2int_rn(v.x * invS),
                      (signed char)__float2int_rn(v.y * invS),
                      (signed char)__float2int_rn(v.z * invS),
                      (signed char)__float2int_rn(v.w * invS));
}

__device__ __forceinline__ void quant_row_body(const float* __restrict__ src, int ncols,
                                               int8_t* __restrict__ q,
                                               float* __restrict__ Srow, int row) {
    __shared__ float red[8];
    const float* r = src + (size_t)row * ncols;
    const int tid = threadIdx.x;
    const int n4 = ncols >> 2;
    float amax = 0.f;
    for (int i = tid; i < n4; i += 256) {
        float4 v = ((const float4*)r)[i];
        amax = fmaxf(amax, fmaxf(fmaxf(fabsf(v.x), fabsf(v.y)), fmaxf(fabsf(v.z), fabsf(v.w))));
    }
    const float m = block_max256(amax, red);
    const float S = fmaxf(m, 1e-20f) * (1.0f / 127.0f);
    const float invS = 1.0f / S;
    for (int i = tid; i < n4; i += 256) {
        float4 v = ((const float4*)r)[i];
        ((char4*)(q + (size_t)row * ncols))[i] = quant4s(v, invS);
    }
    if (tid == 0) Srow[row] = S;
}

__global__ __launch_bounds__(256) void quant_rows(const float* __restrict__ src, int ncols,
                                                  int8_t* __restrict__ q,
                                                  float* __restrict__ S) {
    quant_row_body(src, ncols, q, S, blockIdx.x);
}

__global__ __launch_bounds__(256) void quant_weights(
    const float* qkv_w, const float* o_w, const float* w1, const float* w2,
    int8_t* wq, float* swq, int8_t* wo, float* swo,
    int8_t* w1q, float* sw1, int8_t* w2q, float* sw2) {
    int r = blockIdx.x;
    if (r < 3072)       quant_row_body(qkv_w, 1024, wq,  swq, r);
    else if (r < 4096)  quant_row_body(o_w,   1024, wo,  swo, r - 3072);
    else if (r < 8192)  quant_row_body(w1,    1024, w1q, sw1, r - 4096);
    else                quant_row_body(w2,    4096, w2q, sw2, r - 8192);
}

// ================= rmsnorm -> int8 single-digit =================
__global__ __launch_bounds__(256) void rmsnorm_quant(const float* __restrict__ x,
                                                     int8_t* __restrict__ q,
                                                     float* __restrict__ S) {
    __shared__ float red[8], redm[8];
    const int row = blockIdx.x;
    const int tid = threadIdx.x;
    float4 v = ((const float4*)(x + (size_t)row * DIM))[tid];
    float ss = v.x * v.x + v.y * v.y + v.z * v.z + v.w * v.w;
    float am = fmaxf(fmaxf(fabsf(v.x), fabsf(v.y)), fmaxf(fabsf(v.z), fabsf(v.w)));
    #pragma unroll
    for (int off = 16; off; off >>= 1) {
        ss += __shfl_xor_sync(0xffffffffu, ss, off);
        am = fmaxf(am, __shfl_xor_sync(0xffffffffu, am, off));
    }
    if ((tid & 31) == 0) { red[tid >> 5] = ss; redm[tid >> 5] = am; }
    __syncthreads();
    float tot = 0.f, m = 0.f;
    #pragma unroll
    for (int i = 0; i < 8; i++) { tot += red[i]; m = fmaxf(m, redm[i]); }
    const float r = rsqrtf(tot * (1.0f / DIM) + EPS_F);
    v.x *= r; v.y *= r; v.z *= r; v.w *= r;
    const float Sv = fmaxf(m * r, 1e-20f) * (1.0f / 127.0f);
    ((char4*)(q + (size_t)row * DIM))[tid] = quant4s(v, 1.0f / Sv);
    if (tid == 0) S[row] = Sv;
}

// ================= rope table =================
__global__ __launch_bounds__(256) void rope_tab(float2* __restrict__ tab) {
    const int idx = blockIdx.x * 256 + threadIdx.x;
    const int t = idx >> 4, j = idx & 15;
    const float f = powf(1e-4f, (float)j * (1.0f / 15.0f));
    float sn, cs;
    sincosf((float)t * f, &sn, &cs);
    tab[idx] = make_float2(cs, sn);
}

// ================= per-head q/k rmsnorm + rope; v -> bf16 =================
__global__ __launch_bounds__(256) void qk_prep(const float* __restrict__ qkv,
                                               const float2* __restrict__ rope,
                                               __nv_bfloat16* __restrict__ qb,
                                               __nv_bfloat16* __restrict__ kb,
                                               __nv_bfloat16* __restrict__ vb) {
    const int t    = blockIdx.x;
    const int idx  = blockIdx.y * 8 + (threadIdx.x >> 5);
    const int lane = threadIdx.x & 31;
    const int head = idx & 15;
    const size_t dsto = (size_t)t * DIM + head * HD;
    __nv_bfloat16* dst;
    const float* src;
    if (idx < 16) {
        src = qkv + (size_t)t * QKV_DIM + head * HD;
        dst = qb + dsto;
    } else if (idx < 32) {
        src = qkv + (size_t)t * QKV_DIM + DIM + head * HD;
        dst = kb + dsto;
    } else {
        src = qkv + (size_t)t * QKV_DIM + 2 * DIM + head * HD;
        dst = vb + dsto;
    }
    float a = src[lane];
    float b = src[lane + 32];
    if (idx < 32) {
        float ss = a * a + b * b;
        #pragma unroll
        for (int off = 16; off; off >>= 1) ss += __shfl_xor_sync(0xffffffffu, ss, off);
        const float r = rsqrtf(ss * (1.0f / HD) + EPS_F);
        a *= r; b *= r;
        float sn = 0.f, cs = 1.f;
        if (lane < 16) {
            const float2 e = rope[t * 16 + lane];
            cs = e.x; sn = e.y;
        }
        const float y1 =  a * cs + b * sn;
        const float y2 = -a * sn + b * cs;
        a = y1; b = y2;
    }
    dst[lane]      = __float2bfloat16(a);
    dst[lane + 32] = __float2bfloat16(b);
}

// ================= tensor-core sliding-window attention (plain bf16) ============
#define KVS_B 144
#define KVSPLIT 9216
#define ABUF KVSPLIT                    // Q only
#define KVBUF (2 * KVSPLIT)             // K + V per buffer
#define ATTN_SMEM (ABUF + 2 * KVBUF)    // 46080

__global__ __launch_bounds__(128) void attn_mma(
    const __nv_bfloat16* __restrict__ qb,
    const __nv_bfloat16* __restrict__ kb,
    const __nv_bfloat16* __restrict__ vb,
    float* __restrict__ outf) {
    extern __shared__ char smem[];
    const uint32_t sb = smem_u32(smem);
    const int h    = blockIdx.y;
    const int q0   = blockIdx.x * 64;
    const int tid  = threadIdx.x;
    const int wid  = tid >> 5;
    const int lane = tid & 31;

    #pragma unroll
    for (int it = 0; it < 4; it++) {
        const int g = tid + it * 128;
        const int row = g >> 3, cg = g & 7;
        const size_t src = (size_t)(q0 + row) * DIM + h * HD + cg * 8;
        cp16(sb + (uint32_t)(row * KVS_B + cg * 16), qb + src);
    }
    asm volatile("cp.async.commit_group;" ::: "memory");

    auto load_kv = [&](int kc, int buf) {
        const uint32_t base = sb + ABUF + buf * KVBUF;
        #pragma unroll
        for (int it = 0; it < 4; it++) {
            const int g = tid + it * 128;
            const int row = g >> 3, cg = g & 7;
            const size_t src = (size_t)(kc + row) * DIM + h * HD + cg * 8;
            const uint32_t off = (uint32_t)(row * KVS_B + cg * 16);
            cp16(base + off, kb + src);
            cp16(base + KVSPLIT + off, vb + src);
        }
        asm volatile("cp.async.commit_group;" ::: "memory");
    };

    const int kc0 = (q0 >= WIN) ? (q0 - WIN) : 0;
    const int nch = (q0 + 64 - kc0) >> 6;
    load_kv(kc0, 0);

    asm volatile("cp.async.wait_group 1;" ::: "memory");
    __syncthreads();
    uint32_t qf[16];
    #pragma unroll
    for (int ks = 0; ks < 4; ks++) {
        const uint32_t ad = sb + (uint32_t)((wid * 16 + (lane & 15)) * KVS_B)
                          + ((lane >> 4) * 16) + ks * 32;
        ldsm_x4(qf + ks * 4, ad);
    }

    float m[2] = {-1e30f, -1e30f}, lsum[2] = {0.f, 0.f};
    float o[8][4];
    #pragma unroll
    for (int i = 0; i < 8; i++)
        #pragma unroll
        for (int j = 0; j < 4; j++) o[i][j] = 0.f;

    const int r0 = lane >> 2;
    const int qrow0 = q0 + wid * 16 + r0;
    const int qrow1 = qrow0 + 8;
    const int colb = (lane & 3) * 2;

    for (int c = 0; c < nch; c++) {
        const int b = c & 1;
        const int kc = kc0 + c * 64;
        if (c + 1 < nch) load_kv(kc + 64, b ^ 1);
        if (c + 1 < nch) { asm volatile("cp.async.wait_group 1;" ::: "memory"); }
        else             { asm volatile("cp.async.wait_group 0;" ::: "memory"); }
        __syncthreads();

        const uint32_t Kb = sb + ABUF + b * KVBUF;
        const uint32_t Vb = Kb + KVSPLIT;

        float sc[8][4];
        #pragma unroll
        for (int i = 0; i < 8; i++)
            #pragma unroll
            for (int j = 0; j < 4; j++) sc[i][j] = 0.f;
        #pragma unroll
        for (int ks = 0; ks < 4; ks++) {
            #pragma unroll
            for (int np = 0; np < 4; np++) {
                uint32_t bh4[4];
                const uint32_t bd = Kb
                    + (uint32_t)((np * 16 + ((lane >> 4) * 8) + (lane & 7)) * KVS_B)
                    + (((lane >> 3) & 1) * 16) + ks * 32;
                ldsm_x4(bh4, bd);
                mma16816(sc[np * 2],     qf + ks * 4, bh4);
                mma16816(sc[np * 2 + 1], qf + ks * 4, bh4 + 2);
            }
        }

        #pragma unroll
        for (int nf = 0; nf < 8; nf++) {
            #pragma unroll
            for (int j = 0; j < 4; j++) {
                const int kg = kc + nf * 8 + colb + (j & 1);
                const int q  = (j < 2) ? qrow0 : qrow1;
                const bool valid = (kg <= q) && (kg > q - WIN);
                sc[nf][j] = valid ? sc[nf][j] * 0.125f : -1e30f;
            }
        }
        float mx0 = -1e30f, mx1 = -1e30f;
        #pragma unroll
        for (int nf = 0; nf < 8; nf++) {
            mx0 = fmaxf(mx0, fmaxf(sc[nf][0], sc[nf][1]));
            mx1 = fmaxf(mx1, fmaxf(sc[nf][2], sc[nf][3]));
        }
        #pragma unroll
        for (int off = 1; off <= 2; off <<= 1) {
            mx0 = fmaxf(mx0, __shfl_xor_sync(0xffffffffu, mx0, off));
            mx1 = fmaxf(mx1, __shfl_xor_sync(0xffffffffu, mx1, off));
        }
        const float mn0 = fmaxf(m[0], mx0);
        const float mn1 = fmaxf(m[1], mx1);
        const float cr0 = __expf(m[0] - mn0);
        const float cr1 = __expf(m[1] - mn1);
        m[0] = mn0; m[1] = mn1;
        float sm0 = 0.f, sm1 = 0.f;
        #pragma unroll
        for (int nf = 0; nf < 8; nf++) {
            sc[nf][0] = __expf(sc[nf][0] - mn0);
            sc[nf][1] = __expf(sc[nf][1] - mn0);
            sc[nf][2] = __expf(sc[nf][2] - mn1);
            sc[nf][3] = __expf(sc[nf][3] - mn1);
            sm0 += sc[nf][0] + sc[nf][1];
            sm1 += sc[nf][2] + sc[nf][3];
        }
        #pragma unroll
        for (int off = 1; off <= 2; off <<= 1) {
            sm0 += __shfl_xor_sync(0xffffffffu, sm0, off);
            sm1 += __shfl_xor_sync(0xffffffffu, sm1, off);
        }
        lsum[0] = lsum[0] * cr0 + sm0;
        lsum[1] = lsum[1] * cr1 + sm1;
        #pragma unroll
        for (int nf = 0; nf < 8; nf++) {
            o[nf][0] *= cr0; o[nf][1] *= cr0;
            o[nf][2] *= cr1; o[nf][3] *= cr1;
        }

        #pragma unroll
        for (int ks = 0; ks < 4; ks++) {
            uint32_t ah4[4];
            const float* p0 = sc[ks * 2];
            const float* p1 = sc[ks * 2 + 1];
            ah4[0] = pack_hi(p0[0], p0[1]);
            ah4[1] = pack_hi(p0[2], p0[3]);
            ah4[2] = pack_hi(p1[0], p1[1]);
            ah4[3] = pack_hi(p1[2], p1[3]);
            #pragma unroll
            for (int dg = 0; dg < 4; dg++) {
                uint32_t vh4[4];
                const uint32_t vd = Vb
                    + (uint32_t)((ks * 16 + (lane & 7) + ((lane >> 3) & 1) * 8) * KVS_B)
                    + dg * 32 + (((lane >> 4) & 1) * 16);
                ldsm_x4_t(vh4, vd);
                mma16816(o[dg * 2],     ah4, vh4);
                mma16816(o[dg * 2 + 1], ah4, vh4 + 2);
            }
        }
        __syncthreads();
    }

    const float inv0 = 1.0f / lsum[0];
    const float inv1 = 1.0f / lsum[1];
    #pragma unroll
    for (int nf = 0; nf < 8; nf++) {
        const int col = h * HD + nf * 8 + colb;
        *(float2*)(outf + (size_t)qrow0 * DIM + col) = make_float2(o[nf][0] * inv0, o[nf][1] * inv0);
        *(float2*)(outf + (size_t)qrow1 * DIM + col) = make_float2(o[nf][2] * inv1, o[nf][3] * inv1);
    }
}

// ================= int8 single-digit GEMM v8: mbarrier pipeline, warp 64x64 ======
// CTA 128x128, 128 threads, 4 warps (2x2), warp tile 64x64, k32 stages (8KB,
// XOR-swizzled), 8 stages, per-stage full/empty mbarriers, 2 CTAs co-resident.
// C = Sa[m]*Sb[n]*Ch
#define IBM 128
#define IBN 128
#define NSTG 8
#define STGB 8192
#define IGSMEM (NSTG * STGB + 128)        // 65664

__device__ __forceinline__ uint32_t swz32(uint32_t row, uint32_t g16) {
    return (row * 32u + g16 * 16u) ^ ((row & 4u) << 2);
}

template <int MODE>
__global__ __launch_bounds__(128, 2) void gemm_i8(
    const int8_t* __restrict__ Aq, const float* __restrict__ Sa,
    const int8_t* __restrict__ Bq, const float* __restrict__ Sb,
    int K, int Ntot,
    float* __restrict__ Cf, const float* __restrict__ res, const float* __restrict__ scale) {
    extern __shared__ char smem[];
    const uint32_t sb  = smem_u32(smem);
    const uint32_t mbF = sb + NSTG * STGB;        // full[8]
    const uint32_t mbE = mbF + 64;                // empty[8]
    const int tid  = threadIdx.x;
    const int lane = tid & 31;
    const int wid  = tid >> 5;
    const int wm   = wid >> 1;            // 2 warp rows of 64
    const int wn   = wid & 1;             // 2 warp cols of 64
    const int m0 = blockIdx.y * IBM, n0 = blockIdx.x * IBN;

    int Ch[4][8][4];
    #pragma unroll
    for (int i = 0; i < 4; i++)
        #pragma unroll
        for (int j = 0; j < 8; j++)
            #pragma unroll
            for (int k = 0; k < 4; k++) Ch[i][j][k] = 0;

    if (tid == 0) {
        #pragma unroll
        for (int i = 0; i < NSTG; i++) {
            MBARRIER_INIT(mbF + i * 8, 128);
            MBARRIER_INIT(mbE + i * 8, 128);
        }
    }
    __syncthreads();

    // producer: each thread loads one A row (2x16B) and one B row (2x16B)
    const uint32_t ps0 = swz32((uint32_t)tid, 0u);
    const uint32_t ps1 = swz32((uint32_t)tid, 1u);
    const size_t pa = (size_t)(m0 + tid) * K;
    const size_t pb = (size_t)(n0 + tid) * K;
    auto produce = [&](int c, int stage) {
        const uint32_t base = sb + stage * STGB;
        const int kc = c * 32;
        cp16(base + ps0,        Aq + pa + kc);
        cp16(base + ps1,        Aq + pa + kc + 16);
        cp16(base + 4096 + ps0, Bq + pb + kc);
        cp16(base + 4096 + ps1, Bq + pb + kc + 16);
        CPASYNC_MBAR_ARRIVE(mbF + stage * 8);
    };

    const int NC = K / 32;
    #pragma unroll
    for (int c0 = 0; c0 < NSTG - 1; c0++) produce(c0, c0);

    for (int c = 0; c < NC; c++) {
        const int stg = c & (NSTG - 1);
        const uint32_t stb = sb + stg * STGB;
        MBARRIER_WAIT_PARITY(mbF + stg * 8, (c >> 3) & 1);

        uint32_t ah[16];
        #pragma unroll
        for (int mf = 0; mf < 4; mf++) {
            const uint32_t arow = (uint32_t)(wm * 64 + mf * 16 + (lane & 15));
            ldsm_x4(ah + mf * 4, stb + swz32(arow, (uint32_t)(lane >> 4)));
        }
        #pragma unroll
        for (int g = 0; g < 4; g++) {
            uint32_t bh4[4];
            const uint32_t brow = (uint32_t)(wn * 64 + g * 16 + ((lane >> 4) * 8) + (lane & 7));
            ldsm_x4(bh4, stb + 4096 + swz32(brow, (uint32_t)((lane >> 3) & 1)));
            #pragma unroll
            for (int mf = 0; mf < 4; mf++) {
                imma16832(Ch[mf][g * 2],     ah + mf * 4, bh4);
                imma16832(Ch[mf][g * 2 + 1], ah + mf * 4, bh4 + 2);
            }
        }
        MBARRIER_ARRIVE(mbE + stg * 8);

        const int p = c + NSTG - 1;
        if (p < NC) {
            const int ps = p & (NSTG - 1);
            if (p >= NSTG) MBARRIER_WAIT_PARITY(mbE + ps * 8, ((p >> 3) + 1) & 1);
            produce(p, ps);
        }
    }

    // ---- epilogue ----
    const int rb = m0 + wm * 64 + (lane >> 2);
    const int cb = n0 + wn * 64 + (lane & 3) * 2;
    #pragma unroll
    for (int mf = 0; mf < 4; mf++) {
        const int rr0 = rb + mf * 16;
        const int rr1 = rr0 + 8;
        const float sa0 = Sa[rr0], sa1 = Sa[rr1];
        #pragma unroll
        for (int nf = 0; nf < 8; nf++) {
            const int cn = cb + nf * 8;
            const float2 sbv = *(const float2*)(Sb + cn);
            const int* ch = Ch[mf][nf];
            float v0 = sa0 * sbv.x * (float)ch[0];
            float v1 = sa0 * sbv.y * (float)ch[1];
            float v2 = sa1 * sbv.x * (float)ch[2];
            float v3 = sa1 * sbv.y * (float)ch[3];
            if (MODE == 1) {
                const float2 sc2 = *(const float2*)(scale + cn);
                const float2 q0 = *(const float2*)(res + (size_t)rr0 * Ntot + cn);
                const float2 q1 = *(const float2*)(res + (size_t)rr1 * Ntot + cn);
                v0 = q0.x + sc2.x * v0; v1 = q0.y + sc2.y * v1;
                v2 = q1.x + sc2.x * v2; v3 = q1.y + sc2.y * v3;
            } else if (MODE == 2) {
                v0 = fmaxf(v0, 0.f); v0 *= v0;
                v1 = fmaxf(v1, 0.f); v1 *= v1;
                v2 = fmaxf(v2, 0.f); v2 *= v2;
                v3 = fmaxf(v3, 0.f); v3 *= v3;
            }
            *(float2*)(Cf + (size_t)rr0 * Ntot + cn) = make_float2(v0, v1);
            *(float2*)(Cf + (size_t)rr1 * Ntot + cn) = make_float2(v2, v3);
        }
    }
}

// ================= host launcher =================
extern "C" void kernel_launch(void* const* d_in, const int* in_sizes, int n_in,
                              void* d_out, int out_size) {
    const float* x        = (const float*)d_in[0];
    const float* qkv_w    = (const float*)d_in[1];
    const float* o_w      = (const float*)d_in[2];
    const float* o_scale  = (const float*)d_in[3];
    const float* w1       = (const float*)d_in[4];
    const float* w2       = (const float*)d_in[5];
    const float* w2_scale = (const float*)d_in[6];
    float* out = (float*)d_out;

    float *qkv, *x1, *attn, *hf;
    float2* rope;
    cudaGetSymbolAddress((void**)&qkv,  g_qkv);
    cudaGetSymbolAddress((void**)&x1,   g_x1);
    cudaGetSymbolAddress((void**)&attn, g_attn);
    cudaGetSymbolAddress((void**)&hf,   g_hf);
    cudaGetSymbolAddress((void**)&rope, g_rope);
    __nv_bfloat16 *qb, *kb, *vb;
    cudaGetSymbolAddress((void**)&qb, g_qb);
    cudaGetSymbolAddress((void**)&kb, g_kb);
    cudaGetSymbolAddress((void**)&vb, g_vb);
    int8_t *xq, *aq, *x1q, *hq, *wq, *wo, *w1q, *w2q;
    float *sx, *sa, *sx1, *sh, *swq, *swo, *sw1, *sw2;
    cudaGetSymbolAddress((void**)&xq,  g_xq);  cudaGetSymbolAddress((void**)&aq,  g_aq);
    cudaGetSymbolAddress((void**)&x1q, g_x1q); cudaGetSymbolAddress((void**)&hq,  g_hq);
    cudaGetSymbolAddress((void**)&wq,  g_wq);  cudaGetSymbolAddress((void**)&wo,  g_wo);
    cudaGetSymbolAddress((void**)&w1q, g_w1q); cudaGetSymbolAddress((void**)&w2q, g_w2q);
    cudaGetSymbolAddress((void**)&sx,  g_sx);  cudaGetSymbolAddress((void**)&sa,  g_sa);
    cudaGetSymbolAddress((void**)&sx1, g_sx1); cudaGetSymbolAddress((void**)&sh,  g_sh);
    cudaGetSymbolAddress((void**)&swq, g_swq); cudaGetSymbolAddress((void**)&swo, g_swo);
    cudaGetSymbolAddress((void**)&sw1, g_sw1); cudaGetSymbolAddress((void**)&sw2, g_sw2);

    cudaFuncSetAttribute(gemm_i8<0>, cudaFuncAttributeMaxDynamicSharedMemorySize, IGSMEM);
    cudaFuncSetAttribute(gemm_i8<1>, cudaFuncAttributeMaxDynamicSharedMemorySize, IGSMEM);
    cudaFuncSetAttribute(gemm_i8<2>, cudaFuncAttributeMaxDynamicSharedMemorySize, IGSMEM);
    cudaFuncSetAttribute(attn_mma, cudaFuncAttributeMaxDynamicSharedMemorySize, ATTN_SMEM);

    // 1. all weight quantizations
    quant_weights<<<9216, 256>>>(qkv_w, o_w, w1, w2,
                                 wq, swq, wo, swo, w1q, sw1, w2q, sw2);
    // 2. xn = rmsnorm(x) -> int8
    rmsnorm_quant<<<T_LEN, 256>>>(x, xq, sx);
    // 3. rope table
    rope_tab<<<256, 256>>>(rope);
    // 4. qkv = xn @ qkv_w^T   <-- profiled slot
    gemm_i8<0><<<dim3(QKV_DIM / IBN, T_LEN / IBM), 128, IGSMEM>>>(
        xq, sx, wq, swq, DIM, QKV_DIM, qkv, nullptr, nullptr);
    // 5. q/k norm+rope, v -> bf16
    qk_prep<<<dim3(T_LEN, 6), 256>>>(qkv, rope, qb, kb, vb);
    // 6. attention -> fp32
    attn_mma<<<dim3(T_LEN / 64, NHEADS), 128, ATTN_SMEM>>>(qb, kb, vb, attn);
    // 7. quantize attention output
    quant_rows<<<T_LEN, 256>>>(attn, DIM, aq, sa);
    // 8. x1 = x + o_scale[n] * (attn @ o_w^T)
    gemm_i8<1><<<dim3(DIM / IBN, T_LEN / IBM), 128, IGSMEM>>>(
        aq, sa, wo, swo, DIM, DIM, x1, x, o_scale);
    // 9. x1n = rmsnorm(x1) -> int8
    rmsnorm_quant<<<T_LEN, 256>>>(x1, x1q, sx1);
    // 10. h = relu(x1n @ w1^T)^2 -> fp32
    gemm_i8<2><<<dim3(MLP_DIM / IBN, T_LEN / IBM), 128, IGSMEM>>>(
        x1q, sx1, w1q, sw1, DIM, MLP_DIM, hf, nullptr, nullptr);
    // 11. quantize h
    quant_rows<<<T_LEN, 256>>>(hf, MLP_DIM, hq, sh);
    // 12. out = x1 + w2_scale[n] * (h @ w2^T)
    gemm_i8<1><<<dim3(DIM / IBN, T_LEN / IBM), 128, IGSMEM>>>(
        hq, sh, w2q, sw2, MLP_DIM, DIM, out, x1, w2_scale);
}

// round 16
// speedup vs baseline: 1.2767x; 1.2767x over previous
#include <cuda_runtime.h>
#include <cuda_bf16.h>
#include <math_constants.h>
#include <cstdint>

#define T_LEN   4096
#define DIM     1024
#define QKV_DIM 3072
#define MLP_DIM 4096
#define NHEADS  16
#define HD      64
#define WIN     512
#define EPS_F   1.1920929e-07f

// ================= helpers =================
__device__ __forceinline__ uint32_t smem_u32(const void* p) {
    uint32_t a;
    asm("{ .reg .u64 t; cvta.to.shared.u64 t, %1; cvt.u32.u64 %0, t; }" : "=r"(a) : "l"(p));
    return a;
}
__device__ __forceinline__ void cp16(uint32_t s, const void* g) {
    asm volatile("cp.async.cg.shared.global [%0], [%1], 16;" :: "r"(s), "l"(g));
}
__device__ __forceinline__ void ldsm_x4(uint32_t* r, uint32_t addr) {
    asm volatile("ldmatrix.sync.aligned.m8n8.x4.shared.b16 {%0,%1,%2,%3}, [%4];"
                 : "=r"(r[0]), "=r"(r[1]), "=r"(r[2]), "=r"(r[3]) : "r"(addr));
}
__device__ __forceinline__ void ldsm_x4_t(uint32_t* r, uint32_t addr) {
    asm volatile("ldmatrix.sync.aligned.m8n8.x4.trans.shared.b16 {%0,%1,%2,%3}, [%4];"
                 : "=r"(r[0]), "=r"(r[1]), "=r"(r[2]), "=r"(r[3]) : "r"(addr));
}
__device__ __forceinline__ void mma16816(float* c, const uint32_t* a, const uint32_t* b) {
    asm volatile("mma.sync.aligned.m16n8k16.row.col.f32.bf16.bf16.f32 "
        "{%0,%1,%2,%3}, {%4,%5,%6,%7}, {%8,%9}, {%0,%1,%2,%3};"
        : "+f"(c[0]), "+f"(c[1]), "+f"(c[2]), "+f"(c[3])
        : "r"(a[0]), "r"(a[1]), "r"(a[2]), "r"(a[3]), "r"(b[0]), "r"(b[1]));
}
__device__ __forceinline__ void imma16832(int* c, const uint32_t* a, const uint32_t* b) {
    asm volatile("mma.sync.aligned.m16n8k32.row.col.s32.s8.s8.s32 "
        "{%0,%1,%2,%3}, {%4,%5,%6,%7}, {%8,%9}, {%0,%1,%2,%3};"
        : "+r"(c[0]), "+r"(c[1]), "+r"(c[2]), "+r"(c[3])
        : "r"(a[0]), "r"(a[1]), "r"(a[2]), "r"(a[3]), "r"(b[0]), "r"(b[1]));
}
__device__ __forceinline__ uint32_t pack2(__nv_bfloat16 a, __nv_bfloat16 b) {
    return (uint32_t)__bfloat16_as_ushort(a) | ((uint32_t)__bfloat16_as_ushort(b) << 16);
}
__device__ __forceinline__ uint32_t pack_hi(float a, float b) {
    return pack2(__float2bfloat16(a), __float2bfloat16(b));
}

#define MBARRIER_INIT(addr, cnt) \
    asm volatile("mbarrier.init.shared.b64 [%0], %1;" :: "r"((uint32_t)(addr)), "r"((uint32_t)(cnt)) : "memory")
#define MBARRIER_ARRIVE(addr) \
    asm volatile("mbarrier.arrive.shared::cta.b64 _, [%0];" :: "r"((uint32_t)(addr)) : "memory")
#define CPASYNC_MBAR_ARRIVE(addr) \
    asm volatile("cp.async.mbarrier.arrive.noinc.shared::cta.b64 [%0];" :: "r"((uint32_t)(addr)) : "memory")
#define MBARRIER_WAIT_PARITY(addr, par) do { \
    uint32_t _m = (uint32_t)(addr); uint32_t _p = (uint32_t)(par); uint32_t _d; \
    asm volatile("{\n\t.reg .pred p;\n\tmbarrier.try_wait.parity.acquire.cta.shared::cta.b64 p, [%1], %2;\n\tselp.b32 %0, 1, 0, p;\n\t}" \
        : "=r"(_d) : "r"(_m), "r"(_p) : "memory"); \
    if (!_d) { \
        asm volatile("{\n\t.reg .pred P1;\n\tWL_%=:\n\tmbarrier.try_wait.parity.acquire.cta.shared::cta.b64 P1, [%0], %1, 0x989680;\n\t@P1 bra.uni WD_%=;\n\tbra.uni WL_%=;\n\tWD_%=:\n\t}" \
            :: "r"(_m), "r"(_p) : "memory"); \
    } } while (0)

// ================= scratch =================
__device__ float g_qkv [T_LEN * QKV_DIM];
__device__ float g_x1  [T_LEN * DIM];
__device__ float g_attn[T_LEN * DIM];
__device__ float g_hf  [T_LEN * MLP_DIM];
__device__ float2 g_rope[T_LEN * 16];

#define BF16A __device__ __align__(16) __nv_bfloat16
BF16A g_qb[T_LEN * DIM];
BF16A g_kb[T_LEN * DIM];
BF16A g_vb[T_LEN * DIM];

#define I8A __device__ __align__(16) int8_t
I8A g_xq [T_LEN * DIM];     __device__ float g_sx [T_LEN];
I8A g_aq [T_LEN * DIM];     __device__ float g_sa [T_LEN];
I8A g_x1q[T_LEN * DIM];     __device__ float g_sx1[T_LEN];
I8A g_hq [T_LEN * MLP_DIM]; __device__ float g_sh [T_LEN];
I8A g_wq [QKV_DIM * DIM];   __device__ float g_swq[QKV_DIM];
I8A g_wo [DIM * DIM];       __device__ float g_swo[DIM];
I8A g_w1q[MLP_DIM * DIM];   __device__ float g_sw1[MLP_DIM];
I8A g_w2q[DIM * MLP_DIM];   __device__ float g_sw2[DIM];

// ================= single-digit row quantization =================
__device__ __forceinline__ float block_max256(float v, float* red) {
    #pragma unroll
    for (int off = 16; off; off >>= 1) v = fmaxf(v, __shfl_xor_sync(0xffffffffu, v, off));
    if ((threadIdx.x & 31) == 0) red[threadIdx.x >> 5] = v;
    __syncthreads();
    float m = red[0];
    #pragma unroll
    for (int i = 1; i < 8; i++) m = fmaxf(m, red[i]);
    return m;
}
__device__ __forceinline__ char4 quant4s(float4 v, float invS) {
    return make_char4((signed char)__float2int_rn(v.x * invS),
                      (signed char)__float2int_rn(v.y * invS),
                      (signed char)__float2int_rn(v.z * invS),
                      (signed char)__float2int_rn(v.w * invS));
}

__device__ __forceinline__ void quant_row_body(const float* __restrict__ src, int ncols,
                                               int8_t* __restrict__ q,
                                               float* __restrict__ Srow, int row) {
    __shared__ float red[8];
    const float* r = src + (size_t)row * ncols;
    const int tid = threadIdx.x;
    const int n4 = ncols >> 2;
    float amax = 0.f;
    for (int i = tid; i < n4; i += 256) {
        float4 v = ((const float4*)r)[i];
        amax = fmaxf(amax, fmaxf(fmaxf(fabsf(v.x), fabsf(v.y)), fmaxf(fabsf(v.z), fabsf(v.w))));
    }
    const float m = block_max256(amax, red);
    const float S = fmaxf(m, 1e-20f) * (1.0f / 127.0f);
    const float invS = 1.0f / S;
    for (int i = tid; i < n4; i += 256) {
        float4 v = ((const float4*)r)[i];
        ((char4*)(q + (size_t)row * ncols))[i] = quant4s(v, invS);
    }
    if (tid == 0) Srow[row] = S;
}

__global__ __launch_bounds__(256) void quant_rows(const float* __restrict__ src, int ncols,
                                                  int8_t* __restrict__ q,
                                                  float* __restrict__ S) {
    quant_row_body(src, ncols, q, S, blockIdx.x);
}

__global__ __launch_bounds__(256) void quant_weights(
    const float* qkv_w, const float* o_w, const float* w1, const float* w2,
    int8_t* wq, float* swq, int8_t* wo, float* swo,
    int8_t* w1q, float* sw1, int8_t* w2q, float* sw2) {
    int r = blockIdx.x;
    if (r < 3072)       quant_row_body(qkv_w, 1024, wq,  swq, r);
    else if (r < 4096)  quant_row_body(o_w,   1024, wo,  swo, r - 3072);
    else if (r < 8192)  quant_row_body(w1,    1024, w1q, sw1, r - 4096);
    else                quant_row_body(w2,    4096, w2q, sw2, r - 8192);
}

// ================= rmsnorm -> int8 single-digit =================
__global__ __launch_bounds__(256) void rmsnorm_quant(const float* __restrict__ x,
                                                     int8_t* __restrict__ q,
                                                     float* __restrict__ S) {
    __shared__ float red[8], redm[8];
    const int row = blockIdx.x;
    const int tid = threadIdx.x;
    float4 v = ((const float4*)(x + (size_t)row * DIM))[tid];
    float ss = v.x * v.x + v.y * v.y + v.z * v.z + v.w * v.w;
    float am = fmaxf(fmaxf(fabsf(v.x), fabsf(v.y)), fmaxf(fabsf(v.z), fabsf(v.w)));
    #pragma unroll
    for (int off = 16; off; off >>= 1) {
        ss += __shfl_xor_sync(0xffffffffu, ss, off);
        am = fmaxf(am, __shfl_xor_sync(0xffffffffu, am, off));
    }
    if ((tid & 31) == 0) { red[tid >> 5] = ss; redm[tid >> 5] = am; }
    __syncthreads();
    float tot = 0.f, m = 0.f;
    #pragma unroll
    for (int i = 0; i < 8; i++) { tot += red[i]; m = fmaxf(m, redm[i]); }
    const float r = rsqrtf(tot * (1.0f / DIM) + EPS_F);
    v.x *= r; v.y *= r; v.z *= r; v.w *= r;
    const float Sv = fmaxf(m * r, 1e-20f) * (1.0f / 127.0f);
    ((char4*)(q + (size_t)row * DIM))[tid] = quant4s(v, 1.0f / Sv);
    if (tid == 0) S[row] = Sv;
}

// ================= rope table =================
__global__ __launch_bounds__(256) void rope_tab(float2* __restrict__ tab) {
    const int idx = blockIdx.x * 256 + threadIdx.x;
    const int t = idx >> 4, j = idx & 15;
    const float f = powf(1e-4f, (float)j * (1.0f / 15.0f));
    float sn, cs;
    sincosf((float)t * f, &sn, &cs);
    tab[idx] = make_float2(cs, sn);
}

// ================= per-head q/k rmsnorm + rope; v -> bf16 =================
__global__ __launch_bounds__(256) void qk_prep(const float* __restrict__ qkv,
                                               const float2* __restrict__ rope,
                                               __nv_bfloat16* __restrict__ qb,
                                               __nv_bfloat16* __restrict__ kb,
                                               __nv_bfloat16* __restrict__ vb) {
    const int t    = blockIdx.x;
    const int idx  = blockIdx.y * 8 + (threadIdx.x >> 5);
    const int lane = threadIdx.x & 31;
    const int head = idx & 15;
    const size_t dsto = (size_t)t * DIM + head * HD;
    __nv_bfloat16* dst;
    const float* src;
    if (idx < 16) {
        src = qkv + (size_t)t * QKV_DIM + head * HD;
        dst = qb + dsto;
    } else if (idx < 32) {
        src = qkv + (size_t)t * QKV_DIM + DIM + head * HD;
        dst = kb + dsto;
    } else {
        src = qkv + (size_t)t * QKV_DIM + 2 * DIM + head * HD;
        dst = vb + dsto;
    }
    float a = src[lane];
    float b = src[lane + 32];
    if (idx < 32) {
        float ss = a * a + b * b;
        #pragma unroll
        for (int off = 16; off; off >>= 1) ss += __shfl_xor_sync(0xffffffffu, ss, off);
        const float r = rsqrtf(ss * (1.0f / HD) + EPS_F);
        a *= r; b *= r;
        float sn = 0.f, cs = 1.f;
        if (lane < 16) {
            const float2 e = rope[t * 16 + lane];
            cs = e.x; sn = e.y;
        }
        const float y1 =  a * cs + b * sn;
        const float y2 = -a * sn + b * cs;
        a = y1; b = y2;
    }
    dst[lane]      = __float2bfloat16(a);
    dst[lane + 32] = __float2bfloat16(b);
}

// ================= tensor-core sliding-window attention (plain bf16) ============
#define KVS_B 144
#define KVSPLIT 9216
#define ABUF KVSPLIT                    // Q only
#define KVBUF (2 * KVSPLIT)             // K + V per buffer
#define ATTN_SMEM (ABUF + 2 * KVBUF)    // 46080

__global__ __launch_bounds__(128) void attn_mma(
    const __nv_bfloat16* __restrict__ qb,
    const __nv_bfloat16* __restrict__ kb,
    const __nv_bfloat16* __restrict__ vb,
    float* __restrict__ outf) {
    extern __shared__ char smem[];
    const uint32_t sb = smem_u32(smem);
    const int h    = blockIdx.y;
    const int q0   = blockIdx.x * 64;
    const int tid  = threadIdx.x;
    const int wid  = tid >> 5;
    const int lane = tid & 31;

    #pragma unroll
    for (int it = 0; it < 4; it++) {
        const int g = tid + it * 128;
        const int row = g >> 3, cg = g & 7;
        const size_t src = (size_t)(q0 + row) * DIM + h * HD + cg * 8;
        cp16(sb + (uint32_t)(row * KVS_B + cg * 16), qb + src);
    }
    asm volatile("cp.async.commit_group;" ::: "memory");

    auto load_kv = [&](int kc, int buf) {
        const uint32_t base = sb + ABUF + buf * KVBUF;
        #pragma unroll
        for (int it = 0; it < 4; it++) {
            const int g = tid + it * 128;
            const int row = g >> 3, cg = g & 7;
            const size_t src = (size_t)(kc + row) * DIM + h * HD + cg * 8;
            const uint32_t off = (uint32_t)(row * KVS_B + cg * 16);
            cp16(base + off, kb + src);
            cp16(base + KVSPLIT + off, vb + src);
        }
        asm volatile("cp.async.commit_group;" ::: "memory");
    };

    const int kc0 = (q0 >= WIN) ? (q0 - WIN) : 0;
    const int nch = (q0 + 64 - kc0) >> 6;
    load_kv(kc0, 0);

    asm volatile("cp.async.wait_group 1;" ::: "memory");
    __syncthreads();
    uint32_t qf[16];
    #pragma unroll
    for (int ks = 0; ks < 4; ks++) {
        const uint32_t ad = sb + (uint32_t)((wid * 16 + (lane & 15)) * KVS_B)
                          + ((lane >> 4) * 16) + ks * 32;
        ldsm_x4(qf + ks * 4, ad);
    }

    float m[2] = {-1e30f, -1e30f}, lsum[2] = {0.f, 0.f};
    float o[8][4];
    #pragma unroll
    for (int i = 0; i < 8; i++)
        #pragma unroll
        for (int j = 0; j < 4; j++) o[i][j] = 0.f;

    const int r0 = lane >> 2;
    const int qrow0 = q0 + wid * 16 + r0;
    const int qrow1 = qrow0 + 8;
    const int colb = (lane & 3) * 2;

    for (int c = 0; c < nch; c++) {
        const int b = c & 1;
        const int kc = kc0 + c * 64;
        if (c + 1 < nch) load_kv(kc + 64, b ^ 1);
        if (c + 1 < nch) { asm volatile("cp.async.wait_group 1;" ::: "memory"); }
        else             { asm volatile("cp.async.wait_group 0;" ::: "memory"); }
        __syncthreads();

        const uint32_t Kb = sb + ABUF + b * KVBUF;
        const uint32_t Vb = Kb + KVSPLIT;

        float sc[8][4];
        #pragma unroll
        for (int i = 0; i < 8; i++)
            #pragma unroll
            for (int j = 0; j < 4; j++) sc[i][j] = 0.f;
        #pragma unroll
        for (int ks = 0; ks < 4; ks++) {
            #pragma unroll
            for (int np = 0; np < 4; np++) {
                uint32_t bh4[4];
                const uint32_t bd = Kb
                    + (uint32_t)((np * 16 + ((lane >> 4) * 8) + (lane & 7)) * KVS_B)
                    + (((lane >> 3) & 1) * 16) + ks * 32;
                ldsm_x4(bh4, bd);
                mma16816(sc[np * 2],     qf + ks * 4, bh4);
                mma16816(sc[np * 2 + 1], qf + ks * 4, bh4 + 2);
            }
        }

        #pragma unroll
        for (int nf = 0; nf < 8; nf++) {
            #pragma unroll
            for (int j = 0; j < 4; j++) {
                const int kg = kc + nf * 8 + colb + (j & 1);
                const int q  = (j < 2) ? qrow0 : qrow1;
                const bool valid = (kg <= q) && (kg > q - WIN);
                sc[nf][j] = valid ? sc[nf][j] * 0.125f : -1e30f;
            }
        }
        float mx0 = -1e30f, mx1 = -1e30f;
        #pragma unroll
        for (int nf = 0; nf < 8; nf++) {
            mx0 = fmaxf(mx0, fmaxf(sc[nf][0], sc[nf][1]));
            mx1 = fmaxf(mx1, fmaxf(sc[nf][2], sc[nf][3]));
        }
        #pragma unroll
        for (int off = 1; off <= 2; off <<= 1) {
            mx0 = fmaxf(mx0, __shfl_xor_sync(0xffffffffu, mx0, off));
            mx1 = fmaxf(mx1, __shfl_xor_sync(0xffffffffu, mx1, off));
        }
        const float mn0 = fmaxf(m[0], mx0);
        const float mn1 = fmaxf(m[1], mx1);
        const float cr0 = __expf(m[0] - mn0);
        const float cr1 = __expf(m[1] - mn1);
        m[0] = mn0; m[1] = mn1;
        float sm0 = 0.f, sm1 = 0.f;
        #pragma unroll
        for (int nf = 0; nf < 8; nf++) {
            sc[nf][0] = __expf(sc[nf][0] - mn0);
            sc[nf][1] = __expf(sc[nf][1] - mn0);
            sc[nf][2] = __expf(sc[nf][2] - mn1);
            sc[nf][3] = __expf(sc[nf][3] - mn1);
            sm0 += sc[nf][0] + sc[nf][1];
            sm1 += sc[nf][2] + sc[nf][3];
        }
        #pragma unroll
        for (int off = 1; off <= 2; off <<= 1) {
            sm0 += __shfl_xor_sync(0xffffffffu, sm0, off);
            sm1 += __shfl_xor_sync(0xffffffffu, sm1, off);
        }
        lsum[0] = lsum[0] * cr0 + sm0;
        lsum[1] = lsum[1] * cr1 + sm1;
        #pragma unroll
        for (int nf = 0; nf < 8; nf++) {
            o[nf][0] *= cr0; o[nf][1] *= cr0;
            o[nf][2] *= cr1; o[nf][3] *= cr1;
        }

        #pragma unroll
        for (int ks = 0; ks < 4; ks++) {
            uint32_t ah4[4];
            const float* p0 = sc[ks * 2];
            const float* p1 = sc[ks * 2 + 1];
            ah4[0] = pack_hi(p0[0], p0[1]);
            ah4[1] = pack_hi(p0[2], p0[3]);
            ah4[2] = pack_hi(p1[0], p1[1]);
            ah4[3] = pack_hi(p1[2], p1[3]);
            #pragma unroll
            for (int dg = 0; dg < 4; dg++) {
                uint32_t vh4[4];
                const uint32_t vd = Vb
                    + (uint32_t)((ks * 16 + (lane & 7) + ((lane >> 3) & 1) * 8) * KVS_B)
                    + dg * 32 + (((lane >> 4) & 1) * 16);
                ldsm_x4_t(vh4, vd);
                mma16816(o[dg * 2],     ah4, vh4);
                mma16816(o[dg * 2 + 1], ah4, vh4 + 2);
            }
        }
        __syncthreads();
    }

    const float inv0 = 1.0f / lsum[0];
    const float inv1 = 1.0f / lsum[1];
    #pragma unroll
    for (int nf = 0; nf < 8; nf++) {
        const int col = h * HD + nf * 8 + colb;
        *(float2*)(outf + (size_t)qrow0 * DIM + col) = make_float2(o[nf][0] * inv0, o[nf][1] * inv0);
        *(float2*)(outf + (size_t)qrow1 * DIM + col) = make_float2(o[nf][2] * inv1, o[nf][3] * inv1);
    }
}

// ================= int8 single-digit GEMM (R13 config): mbarrier pipeline =========
// CTA 128x128, 256 threads, 8 warps (2x4), warp tile 64x32, k32 stages (8KB,
// XOR-swizzled), 8 stages, per-stage full/empty mbarriers, no __syncthreads in
// mainloop; 2 CTAs co-resident.  C = Sa[m]*Sb[n]*Ch
#define IBM 128
#define IBN 128
#define NSTG 8
#define STGB 8192
#define IGSMEM (NSTG * STGB + 128)        // 65664

__device__ __forceinline__ uint32_t swz32(uint32_t row, uint32_t g16) {
    return (row * 32u + g16 * 16u) ^ ((row & 4u) << 2);
}

template <int MODE>
__global__ __launch_bounds__(256, 2) void gemm_i8(
    const int8_t* __restrict__ Aq, const float* __restrict__ Sa,
    const int8_t* __restrict__ Bq, const float* __restrict__ Sb,
    int K, int Ntot,
    float* __restrict__ Cf, const float* __restrict__ res, const float* __restrict__ scale) {
    extern __shared__ char smem[];
    const uint32_t sb  = smem_u32(smem);
    const uint32_t mbF = sb + NSTG * STGB;        // full[8]
    const uint32_t mbE = mbF + 64;                // empty[8]
    const int tid  = threadIdx.x;
    const int lane = tid & 31;
    const int wid  = tid >> 5;
    const int wm   = wid >> 2;            // 2 warp rows of 64
    const int wn   = wid & 3;             // 4 warp cols of 32
    const int m0 = blockIdx.y * IBM, n0 = blockIdx.x * IBN;

    int Ch[4][4][4];
    #pragma unroll
    for (int i = 0; i < 4; i++)
        #pragma unroll
        for (int j = 0; j < 4; j++)
            #pragma unroll
            for (int k = 0; k < 4; k++) Ch[i][j][k] = 0;

    if (tid == 0) {
        #pragma unroll
        for (int i = 0; i < NSTG; i++) {
            MBARRIER_INIT(mbF + i * 8, 256);
            MBARRIER_INIT(mbE + i * 8, 256);
        }
    }
    __syncthreads();

    // producer: each thread loads one 16B granule of A and one of B
    const int prow = tid >> 1, pg = tid & 1;
    const uint32_t pso = swz32((uint32_t)prow, (uint32_t)pg);
    const size_t pa = (size_t)(m0 + prow) * K + pg * 16;
    const size_t pb = (size_t)(n0 + prow) * K + pg * 16;
    auto produce = [&](int c, int stage) {
        const uint32_t base = sb + stage * STGB;
        const int kc = c * 32;
        cp16(base + pso,        Aq + pa + kc);
        cp16(base + 4096 + pso, Bq + pb + kc);
        CPASYNC_MBAR_ARRIVE(mbF + stage * 8);
    };

    const int NC = K / 32;
    #pragma unroll
    for (int c0 = 0; c0 < NSTG - 1; c0++) produce(c0, c0);

    for (int c = 0; c < NC; c++) {
        const int stg = c & (NSTG - 1);
        const uint32_t stb = sb + stg * STGB;
        MBARRIER_WAIT_PARITY(mbF + stg * 8, (c >> 3) & 1);

        uint32_t ah[16];
        #pragma unroll
        for (int mf = 0; mf < 4; mf++) {
            const uint32_t arow = (uint32_t)(wm * 64 + mf * 16 + (lane & 15));
            ldsm_x4(ah + mf * 4, stb + swz32(arow, (uint32_t)(lane >> 4)));
        }
        #pragma unroll
        for (int g = 0; g < 2; g++) {
            uint32_t bh4[4];
            const uint32_t brow = (uint32_t)(wn * 32 + g * 16 + ((lane >> 4) * 8) + (lane & 7));
            ldsm_x4(bh4, stb + 4096 + swz32(brow, (uint32_t)((lane >> 3) & 1)));
            #pragma unroll
            for (int mf = 0; mf < 4; mf++) {
                imma16832(Ch[mf][g * 2],     ah + mf * 4, bh4);
                imma16832(Ch[mf][g * 2 + 1], ah + mf * 4, bh4 + 2);
            }
        }
        MBARRIER_ARRIVE(mbE + stg * 8);

        const int p = c + NSTG - 1;
        if (p < NC) {
            const int ps = p & (NSTG - 1);
            if (p >= NSTG) MBARRIER_WAIT_PARITY(mbE + ps * 8, ((p >> 3) + 1) & 1);
            produce(p, ps);
        }
    }

    // ---- epilogue ----
    const int rb = m0 + wm * 64 + (lane >> 2);
    const int cb = n0 + wn * 32 + (lane & 3) * 2;
    #pragma unroll
    for (int mf = 0; mf < 4; mf++) {
        const int rr0 = rb + mf * 16;
        const int rr1 = rr0 + 8;
        const float sa0 = Sa[rr0], sa1 = Sa[rr1];
        #pragma unroll
        for (int nf = 0; nf < 4; nf++) {
            const int cn = cb + nf * 8;
            const float2 sbv = *(const float2*)(Sb + cn);
            const int* ch = Ch[mf][nf];
            float v0 = sa0 * sbv.x * (float)ch[0];
            float v1 = sa0 * sbv.y * (float)ch[1];
            float v2 = sa1 * sbv.x * (float)ch[2];
            float v3 = sa1 * sbv.y * (float)ch[3];
            if (MODE == 1) {
                const float2 sc2 = *(const float2*)(scale + cn);
                const float2 q0 = *(const float2*)(res + (size_t)rr0 * Ntot + cn);
                const float2 q1 = *(const float2*)(res + (size_t)rr1 * Ntot + cn);
                v0 = q0.x + sc2.x * v0; v1 = q0.y + sc2.y * v1;
                v2 = q1.x + sc2.x * v2; v3 = q1.y + sc2.y * v3;
            } else if (MODE == 2) {
                v0 = fmaxf(v0, 0.f); v0 *= v0;
                v1 = fmaxf(v1, 0.f); v1 *= v1;
                v2 = fmaxf(v2, 0.f); v2 *= v2;
                v3 = fmaxf(v3, 0.f); v3 *= v3;
            }
            *(float2*)(Cf + (size_t)rr0 * Ntot + cn) = make_float2(v0, v1);
            *(float2*)(Cf + (size_t)rr1 * Ntot + cn) = make_float2(v2, v3);
        }
    }
}

// ================= host launcher =================
extern "C" void kernel_launch(void* const* d_in, const int* in_sizes, int n_in,
                              void* d_out, int out_size) {
    const float* x        = (const float*)d_in[0];
    const float* qkv_w    = (const float*)d_in[1];
    const float* o_w      = (const float*)d_in[2];
    const float* o_scale  = (const float*)d_in[3];
    const float* w1       = (const float*)d_in[4];
    const float* w2       = (const float*)d_in[5];
    const float* w2_scale = (const float*)d_in[6];
    float* out = (float*)d_out;

    float *qkv, *x1, *attn, *hf;
    float2* rope;
    cudaGetSymbolAddress((void**)&qkv,  g_qkv);
    cudaGetSymbolAddress((void**)&x1,   g_x1);
    cudaGetSymbolAddress((void**)&attn, g_attn);
    cudaGetSymbolAddress((void**)&hf,   g_hf);
    cudaGetSymbolAddress((void**)&rope, g_rope);
    __nv_bfloat16 *qb, *kb, *vb;
    cudaGetSymbolAddress((void**)&qb, g_qb);
    cudaGetSymbolAddress((void**)&kb, g_kb);
    cudaGetSymbolAddress((void**)&vb, g_vb);
    int8_t *xq, *aq, *x1q, *hq, *wq, *wo, *w1q, *w2q;
    float *sx, *sa, *sx1, *sh, *swq, *swo, *sw1, *sw2;
    cudaGetSymbolAddress((void**)&xq,  g_xq);  cudaGetSymbolAddress((void**)&aq,  g_aq);
    cudaGetSymbolAddress((void**)&x1q, g_x1q); cudaGetSymbolAddress((void**)&hq,  g_hq);
    cudaGetSymbolAddress((void**)&wq,  g_wq);  cudaGetSymbolAddress((void**)&wo,  g_wo);
    cudaGetSymbolAddress((void**)&w1q, g_w1q); cudaGetSymbolAddress((void**)&w2q, g_w2q);
    cudaGetSymbolAddress((void**)&sx,  g_sx);  cudaGetSymbolAddress((void**)&sa,  g_sa);
    cudaGetSymbolAddress((void**)&sx1, g_sx1); cudaGetSymbolAddress((void**)&sh,  g_sh);
    cudaGetSymbolAddress((void**)&swq, g_swq); cudaGetSymbolAddress((void**)&swo, g_swo);
    cudaGetSymbolAddress((void**)&sw1, g_sw1); cudaGetSymbolAddress((void**)&sw2, g_sw2);

    cudaFuncSetAttribute(gemm_i8<0>, cudaFuncAttributeMaxDynamicSharedMemorySize, IGSMEM);
    cudaFuncSetAttribute(gemm_i8<1>, cudaFuncAttributeMaxDynamicSharedMemorySize, IGSMEM);
    cudaFuncSetAttribute(gemm_i8<2>, cudaFuncAttributeMaxDynamicSharedMemorySize, IGSMEM);
    cudaFuncSetAttribute(attn_mma, cudaFuncAttributeMaxDynamicSharedMemorySize, ATTN_SMEM);

    // 1. all weight quantizations
    quant_weights<<<9216, 256>>>(qkv_w, o_w, w1, w2,
                                 wq, swq, wo, swo, w1q, sw1, w2q, sw2);
    // 2. xn = rmsnorm(x) -> int8
    rmsnorm_quant<<<T_LEN, 256>>>(x, xq, sx);
    // 3. rope table
    rope_tab<<<256, 256>>>(rope);
    // 4. qkv = xn @ qkv_w^T   <-- profiled slot
    gemm_i8<0><<<dim3(QKV_DIM / IBN, T_LEN / IBM), 256, IGSMEM>>>(
        xq, sx, wq, swq, DIM, QKV_DIM, qkv, nullptr, nullptr);
    // 5. q/k norm+rope, v -> bf16
    qk_prep<<<dim3(T_LEN, 6), 256>>>(qkv, rope, qb, kb, vb);
    // 6. attention -> fp32
    attn_mma<<<dim3(T_LEN / 64, NHEADS), 128, ATTN_SMEM>>>(qb, kb, vb, attn);
    // 7. quantize attention output
    quant_rows<<<T_LEN, 256>>>(attn, DIM, aq, sa);
    // 8. x1 = x + o_scale[n] * (attn @ o_w^T)
    gemm_i8<1><<<dim3(DIM / IBN, T_LEN / IBM), 256, IGSMEM>>>(
        aq, sa, wo, swo, DIM, DIM, x1, x, o_scale);
    // 9. x1n = rmsnorm(x1) -> int8
    rmsnorm_quant<<<T_LEN, 256>>>(x1, x1q, sx1);
    // 10. h = relu(x1n @ w1^T)^2 -> fp32
    gemm_i8<2><<<dim3(MLP_DIM / IBN, T_LEN / IBM), 256, IGSMEM>>>(
        x1q, sx1, w1q, sw1, DIM, MLP_DIM, hf, nullptr, nullptr);
    // 11. quantize h
    quant_rows<<<T_LEN, 256>>>(hf, MLP_DIM, hq, sh);
    // 12. out = x1 + w2_scale[n] * (h @ w2^T)
    gemm_i8<1><<<dim3(DIM / IBN, T_LEN / IBM), 256, IGSMEM>>>(
        hq, sh, w2q, sw2, MLP_DIM, DIM, out, x1, w2_scale);
}